// round 17
// baseline (speedup 1.0000x reference)
#include <cuda_runtime.h>
#include <cuda_fp16.h>
#include <cstdint>

// VanillaRNN on GB300 — Round 16: GEMM1 at mma.sync floor (keep R13);
// fix GEMM3 wave quantization (128x64 tiles, 1024 CTAs, 2 CTAs/SM) and
// fuse all fp32->fp16 conversions into one launch.
//
//   new_state = ReLU(X@W_in^T + state@W_rec^T + b_in + b_rec)  [8192,4096]
//   out       = ReLU(new_state@W_out^T + b_out)                [8192,1024]
// d_out = (out, new_state) fp32.
//
// GEMM template: BM=128 fixed, 4 m-warps x WARPS_N n-warps, warp tile
// 32 x (BN/WARPS_N), BK=64, 3-stage cp.async ring, one barrier/iter,
// ldmatrix.m8n8.x4.b16 fragment feeding (mapping verified R6/R11).
//   GEMM1: BN=256, WARPS_N=4 (512 thr)  -> 97% of 2048 FLOP/cyc/SM floor
//   GEMM3: BN=64,  WARPS_N=2 (256 thr)  -> grid 1024, ~7 waves, 2 CTAs/SM

#define BM 128
#define BK 64
#define STAGES 3
#define SROWH 72                            // halves per smem row (64+8 pad)=144B
#define A_HALVES (BM * SROWH)               // 9216

// ---- fp16 scratch (static device globals; allowed scratch mechanism) ----
__device__ __align__(16) __half g_hX[8192 * 1024];
__device__ __align__(16) __half g_hState[8192 * 4096];
__device__ __align__(16) __half g_hWin[4096 * 1024];
__device__ __align__(16) __half g_hWrec[4096 * 4096];
__device__ __align__(16) __half g_hWout[1024 * 4096];
__device__ __align__(16) __half g_hNew[8192 * 4096];

__device__ __forceinline__ uint32_t s2u(const void* p) {
    uint32_t a;
    asm("{ .reg .u64 t; cvta.to.shared.u64 t, %1; cvt.u32.u64 %0, t; }" : "=r"(a) : "l"(p));
    return a;
}

#define CP16(dst, src) \
    asm volatile("cp.async.cg.shared.global [%0], [%1], 16;" :: "r"(dst), "l"(src))
#define CP_COMMIT() asm volatile("cp.async.commit_group;" ::: "memory")
#define CP_WAIT(N)  asm volatile("cp.async.wait_group %0;" :: "n"(N) : "memory")

#define LDSM4(r0, r1, r2, r3, addr)                                            \
    asm volatile("ldmatrix.sync.aligned.m8n8.x4.shared.b16 {%0,%1,%2,%3}, [%4];" \
                 : "=r"(r0), "=r"(r1), "=r"(r2), "=r"(r3) : "r"(addr))

#define MMA_F16(ac, a0, a1, a2, a3, b0, b1)                                    \
    asm volatile(                                                              \
        "mma.sync.aligned.m16n8k16.row.col.f32.f16.f16.f32 "                   \
        "{%0,%1,%2,%3}, {%4,%5,%6,%7}, {%8,%9}, {%0,%1,%2,%3};"                \
        : "+f"((ac)[0]), "+f"((ac)[1]), "+f"((ac)[2]), "+f"((ac)[3])           \
        : "r"(a0), "r"(a1), "r"(a2), "r"(a3), "r"(b0), "r"(b1))

// ---- fused fp32 -> fp16 RN converter: all five tensors, one launch ----
// segment n4 sizes (float4 units): X 2097152 | state 8388608 | W_in 1048576
// | W_rec 4194304 | W_out 1048576 ; total = 16777216 = 2^24
__global__ void __launch_bounds__(256) f2h_all(
    const float4* __restrict__ sX, const float4* __restrict__ sS,
    const float4* __restrict__ sWi, const float4* __restrict__ sWr,
    const float4* __restrict__ sWo)
{
    const int NSEG = 5;
    const unsigned cum[NSEG + 1] = {0u, 2097152u, 10485760u, 11534336u,
                                    15728640u, 16777216u};
    const float4* srcs[NSEG] = {sX, sS, sWi, sWr, sWo};
    __half* dsts[NSEG] = {g_hX, g_hState, g_hWin, g_hWrec, g_hWout};

    unsigned i = blockIdx.x * blockDim.x + threadIdx.x;
    const unsigned stride = gridDim.x * blockDim.x;
#pragma unroll 1
    for (; i < 16777216u; i += stride) {
        int seg = 0;
#pragma unroll
        for (int k = 1; k < NSEG; k++) seg += (i >= cum[k]);
        const unsigned off = i - cum[seg];
        float4 v = srcs[seg][off];
        __half2 h0 = __floats2half2_rn(v.x, v.y);
        __half2 h1 = __floats2half2_rn(v.z, v.w);
        uint2 pk;
        pk.x = *(uint32_t*)&h0;
        pk.y = *(uint32_t*)&h1;
        *(uint2*)(dsts[seg] + 4 * (size_t)off) = pk;
    }
}

// ---- templated GEMM: C = ReLU(A1@B1^T + A2@B2^T + biases), NT fp16 ----
template <int BN_, int WARPS_N>
__global__ void __launch_bounds__(128 * WARPS_N) rnn_gemm_h(
    const __half* __restrict__ A1, int lda1,
    const __half* __restrict__ B1, int ldb1, int n1,
    const __half* __restrict__ A2, int lda2,
    const __half* __restrict__ B2, int ldb2, int n2,
    const float* __restrict__ bias1, const float* __restrict__ bias2,
    float* __restrict__ C, int ldc, __half* __restrict__ hC)
{
    constexpr int THREADS_T = 128 * WARPS_N;
    constexpr int WTN  = BN_ / WARPS_N;          // warp tile n (64 or 32)
    constexpr int NJ   = WTN / 8;                // n8 tiles per warp (8 or 4)
    constexpr int NJP  = NJ / 2;                 // B x4-LDSM per ks (4 or 2)
    constexpr int B_HALVES_T = BN_ * SROWH;
    constexpr int STAGE_B = (A_HALVES + B_HALVES_T) * 2;
    constexpr int ACHUNKS = BM * 8;              // 1024
    constexpr int BCHUNKS = BN_ * 8;
    constexpr int PER_THR = (ACHUNKS + BCHUNKS) / THREADS_T;  // 6 both cfgs

    extern __shared__ __align__(16) char smem[];
    const uint32_t sbase = s2u(smem);

    const int tid  = threadIdx.x;
    const int warp = tid >> 5;
    const int lane = tid & 31;
    const int tg   = lane & 3;
    const int g    = lane >> 2;
    const int wm   = warp / WARPS_N;   // 0..3, rows wm*32..+32
    const int wn   = warp % WARPS_N;   // cols wn*WTN..+WTN

    const int rowBase = blockIdx.y * BM;
    const int colBase = blockIdx.x * BN_;
    const int niters  = n1 + n2;

    const uint32_t laneOff = (uint32_t)(lane & 15) * (SROWH * 2) + ((lane >> 4) << 4);

    float acc[2][NJ][4];
#pragma unroll
    for (int i = 0; i < 2; i++)
#pragma unroll
        for (int j = 0; j < NJ; j++)
#pragma unroll
            for (int v = 0; v < 4; v++) acc[i][j][v] = 0.0f;

    auto load_stage = [&](int j, int s) {
        const __half* Ab; const __half* Bb; int lda, ldb, ko;
        if (j < n1) { Ab = A1; Bb = B1; lda = lda1; ldb = ldb1; ko = j * BK; }
        else        { Ab = A2; Bb = B2; lda = lda2; ldb = ldb2; ko = (j - n1) * BK; }
        const uint32_t base = sbase + s * STAGE_B;
#pragma unroll
        for (int kk = 0; kk < PER_THR; kk++) {
            const int c = tid + kk * THREADS_T;
            if (c < ACHUNKS) {
                const int r  = c >> 3;
                const int ch = c & 7;
                CP16(base + r * (SROWH * 2) + ch * 16,
                     Ab + (size_t)(rowBase + r) * lda + ko + ch * 8);
            } else {
                const int cb = c - ACHUNKS;
                const int r  = cb >> 3;
                const int ch = cb & 7;
                CP16(base + A_HALVES * 2 + r * (SROWH * 2) + ch * 16,
                     Bb + (size_t)(colBase + r) * ldb + ko + ch * 8);
            }
        }
    };

    load_stage(0, 0); CP_COMMIT();
    load_stage(1, 1); CP_COMMIT();

#pragma unroll 1
    for (int it = 0; it < niters; ++it) {
        const int s = it % STAGES;
        if (it < niters - 1) { CP_WAIT(1); } else { CP_WAIT(0); }
        __syncthreads();

        if (it + 2 < niters) { load_stage(it + 2, (it + 2) % STAGES); CP_COMMIT(); }

        const uint32_t stA = sbase + s * STAGE_B
                           + (uint32_t)(wm * 32) * (SROWH * 2);
        const uint32_t stB = sbase + s * STAGE_B + A_HALVES * 2
                           + (uint32_t)(wn * WTN) * (SROWH * 2);

#pragma unroll
        for (int ks = 0; ks < 4; ks++) {
            const uint32_t ko = (uint32_t)(ks * 32) + laneOff;
            uint32_t fa[8], fb[4 * NJP];
#pragma unroll
            for (int i = 0; i < 2; i++)
                LDSM4(fa[4 * i], fa[4 * i + 1], fa[4 * i + 2], fa[4 * i + 3],
                      stA + ko + (uint32_t)(i * 16) * (SROWH * 2));
#pragma unroll
            for (int jp = 0; jp < NJP; jp++)
                LDSM4(fb[4 * jp], fb[4 * jp + 1], fb[4 * jp + 2], fb[4 * jp + 3],
                      stB + ko + (uint32_t)(jp * 16) * (SROWH * 2));

#pragma unroll
            for (int i = 0; i < 2; i++)
#pragma unroll
                for (int j = 0; j < NJ; j++) {
                    const int jp = j >> 1, jo = j & 1;
                    MMA_F16(acc[i][j],
                            fa[4 * i], fa[4 * i + 1], fa[4 * i + 2], fa[4 * i + 3],
                            fb[4 * jp + jo], fb[4 * jp + 2 + jo]);
                }
        }
    }

    // ---- epilogue ----
    float2 bv[NJ];
#pragma unroll
    for (int j = 0; j < NJ; j++) {
        const int c = colBase + wn * WTN + j * 8 + 2 * tg;
        float2 b = *(const float2*)(bias1 + c);
        if (bias2) {
            float2 b2 = *(const float2*)(bias2 + c);
            b.x += b2.x; b.y += b2.y;
        }
        bv[j] = b;
    }
#pragma unroll
    for (int i = 0; i < 2; i++) {
        const int r0 = rowBase + wm * 32 + i * 16 + g;
#pragma unroll
        for (int j = 0; j < NJ; j++) {
            const int c = colBase + wn * WTN + j * 8 + 2 * tg;
            float2 v0, v1;
            v0.x = fmaxf(acc[i][j][0] + bv[j].x, 0.0f);
            v0.y = fmaxf(acc[i][j][1] + bv[j].y, 0.0f);
            v1.x = fmaxf(acc[i][j][2] + bv[j].x, 0.0f);
            v1.y = fmaxf(acc[i][j][3] + bv[j].y, 0.0f);
            *(float2*)&C[(size_t)r0 * ldc + c]       = v0;
            *(float2*)&C[(size_t)(r0 + 8) * ldc + c] = v1;
            if (hC) {
                __half2 h0 = __floats2half2_rn(v0.x, v0.y);
                __half2 h1 = __floats2half2_rn(v1.x, v1.y);
                *(__half2*)(hC + (size_t)r0 * ldc + c)       = h0;
                *(__half2*)(hC + (size_t)(r0 + 8) * ldc + c) = h1;
            }
        }
    }
}

// force eager module load (incl. device globals) before harness checkpoints
namespace {
struct EagerInit {
    EagerInit() { void* p = nullptr; cudaGetSymbolAddress(&p, g_hX); }
};
EagerInit s_eager;
}

extern "C" void kernel_launch(void* const* d_in, const int* in_sizes, int n_in,
                              void* d_out, int out_size)
{
    (void)in_sizes; (void)n_in; (void)out_size;
    const int B_ = 8192, DIN = 1024, H_ = 4096, DO_ = 1024;

    const float* X     = (const float*)d_in[0];
    const float* state = (const float*)d_in[1];
    const float* W_in  = (const float*)d_in[2];
    const float* b_in  = (const float*)d_in[3];
    const float* W_rec = (const float*)d_in[4];
    const float* b_rec = (const float*)d_in[5];
    const float* W_out = (const float*)d_in[6];
    const float* b_out = (const float*)d_in[7];

    float* out       = (float*)d_out;                     // [B, D_OUT]
    float* new_state = (float*)d_out + (size_t)B_ * DO_;  // [B, H]

    constexpr int SMEM1 = STAGES * ((A_HALVES + 256 * SROWH) * 2);  // 165888
    constexpr int SMEM3 = STAGES * ((A_HALVES + 64 * SROWH) * 2);   // 82944

    static __half *hX, *hState, *hWin, *hWrec, *hWout, *hNew;
    static int inited = 0;
    if (!inited) {
        cudaFuncSetAttribute(rnn_gemm_h<256, 4>,
                             cudaFuncAttributeMaxDynamicSharedMemorySize, SMEM1);
        cudaFuncSetAttribute(rnn_gemm_h<64, 2>,
                             cudaFuncAttributeMaxDynamicSharedMemorySize, SMEM3);
        cudaGetSymbolAddress((void**)&hX,     g_hX);
        cudaGetSymbolAddress((void**)&hState, g_hState);
        cudaGetSymbolAddress((void**)&hWin,   g_hWin);
        cudaGetSymbolAddress((void**)&hWrec,  g_hWrec);
        cudaGetSymbolAddress((void**)&hWout,  g_hWout);
        cudaGetSymbolAddress((void**)&hNew,   g_hNew);
        inited = 1;
    }

    // ---- fused fp32 -> fp16 conversion (one launch, grid-stride) ----
    f2h_all<<<8192, 256>>>((const float4*)X, (const float4*)state,
                           (const float4*)W_in, (const float4*)W_rec,
                           (const float4*)W_out);

    // GEMM1+2 fused along K: new_state = ReLU(X@W_in^T + state@W_rec^T + b)
    {
        dim3 grid(H_ / 256, B_ / BM);   // (16, 64)
        rnn_gemm_h<256, 4><<<grid, 512, SMEM1>>>(
            hX, DIN, hWin, DIN, DIN / BK,
            hState, H_, hWrec, H_, H_ / BK,
            b_in, b_rec, new_state, H_, hNew);
    }
    // GEMM3: out = ReLU(new_state@W_out^T + b_out)  — 128x64 tiles, 1024 CTAs
    {
        dim3 grid(DO_ / 64, B_ / BM);   // (16, 64)
        rnn_gemm_h<64, 2><<<grid, 256, SMEM3>>>(
            hNew, H_, hWout, H_, H_ / BK,
            nullptr, 0, nullptr, 0, 0,
            b_out, nullptr, out, DO_, nullptr);
    }
}